// round 8
// baseline (speedup 1.0000x reference)
#include <cuda_runtime.h>

// Problem constants
static constexpr int   N_PTS   = 16384;
static constexpr int   C_DIM   = 16;
static constexpr int   H_DIM   = 32;
static constexpr int   KNN     = 9;
static constexpr float UPD_RATE = 1e-4f;

// Spatial grid: 128x128 over [-5,5]; ~16 pts/cell at Gaussian peak.
static constexpr int   GG  = 128;
static constexpr float GB  = 5.0f;
static constexpr int   CAP = 64;
static constexpr float CS  = 2.0f * GB / GG;
static constexpr float INV_CS = GG / (2.0f * GB);
static constexpr int   NCELL = GG * GG;          // 16384

// Scratch (device globals: allocation-free per harness rules)
__device__ __align__(16) float  g_x [N_PTS * C_DIM];
__device__ __align__(16) float  g_ha[N_PTS * H_DIM];
__device__ __align__(16) float  g_hb[N_PTS * H_DIM];
__device__ int    g_idx[N_PTS * KNN];
__device__ int    g_cnt[NCELL];
__device__ float4 g_pts[NCELL * CAP];      // (x, y, bitcast(id), 0)

__device__ __forceinline__ int cell_coord(float v) {
    int c = (int)floorf((v + GB) * INV_CS);
    c = c < 0 ? 0 : c;
    c = c > GG - 1 ? GG - 1 : c;
    return c;
}

__device__ __forceinline__ void bin_insert(float px, float py, int id) {
    int b = cell_coord(py) * GG + cell_coord(px);
    int s = atomicAdd(&g_cnt[b], 1);
    if (s < CAP) g_pts[b * CAP + s] = make_float4(px, py, __int_as_float(id), 0.0f);
}

// ---------------------------------------------------------------------------
__global__ void k_copy_in(const float* __restrict__ src) {
    int i = blockIdx.x * blockDim.x + threadIdx.x;     // 65536 threads
    ((float4*)g_x)[i] = ((const float4*)src)[i];
    if (i < NCELL) g_cnt[i] = 0;
}

__global__ void k_binfill() {
    int i = blockIdx.x * blockDim.x + threadIdx.x;
    if (i >= N_PTS) return;
    bin_insert(g_x[i * C_DIM + 0], g_x[i * C_DIM + 1], i);
}

// ---------------------------------------------------------------------------
// Cell-centric kNN, smem-staged candidates:
//  - one warp per grid cell; lane = resident query point
//  - each candidate cell's points loaded 32-wide into a per-warp smem tile,
//    then scanned via pipelined LDS broadcasts (all lanes, private top-9)
//  - exact per-query box termination; no cross-lane merge needed.
__global__ void __launch_bounds__(256) k_knn() {
    __shared__ float4 sbuf[8][CAP];       // 8 warps x 64 x 16B = 8KB

    const int w    = threadIdx.x >> 5;
    const int lane = threadIdx.x & 31;
    const int cell = blockIdx.x * 8 + w;
    if (cell >= NCELL) return;

    int qcnt = g_cnt[cell];
    qcnt = qcnt < CAP ? qcnt : CAP;
    if (qcnt == 0) return;

    const int cx = cell & (GG - 1);
    const int cy = cell >> 7;

    const float INF = __int_as_float(0x7f800000);

    for (int qb = 0; qb < qcnt; qb += 32) {
        int  qi  = qb + lane;
        bool has = (qi < qcnt);
        float4 qp = has ? g_pts[cell * CAP + qi]
                        : make_float4(1e38f, 1e38f, __int_as_float(0), 0.0f);
        const float qx = qp.x;
        const float qy = qp.y;
        const int   q  = __float_as_int(qp.z);

        float bd[KNN];
        int   bi[KNN];
#pragma unroll
        for (int p = 0; p < KNN; ++p) { bd[p] = INF; bi[p] = q; }

        // Stage cell bb's cc points into smem (parallel), then scan (LDS).
        auto stage_and_scan = [&](int bb, int cc) {
            const float4* pp = &g_pts[bb * CAP];
            if (lane < cc)            sbuf[w][lane]      = pp[lane];
            if (32 + lane < cc)       sbuf[w][32 + lane] = pp[32 + lane];
            __syncwarp();
            for (int t = 0; t < cc; ++t) {
                float4 p = sbuf[w][t];               // smem broadcast
                float dx = qx - p.x;
                float dy = qy - p.y;
                float d2 = __fadd_rn(__fmul_rn(dx, dx), __fmul_rn(dy, dy));
                if (d2 < bd[KNN - 1]) {
                    float cd = d2;
                    int   ci = __float_as_int(p.z);
#pragma unroll
                    for (int pos = 0; pos < KNN; ++pos) {
                        if (cd < bd[pos]) {
                            float tf = bd[pos]; bd[pos] = cd; cd = tf;
                            int   ti = bi[pos]; bi[pos] = ci; ci = ti;
                        }
                    }
                }
            }
            __syncwarp();
        };

        stage_and_scan(cell, qcnt);   // ring 0 (home cell)

        for (int r = 1; r < 2 * GG; ++r) {
            int nc = 8 * r;
            for (int base = 0; base < nc; base += 32) {
                int i = base + lane;
                int b2 = 0, c2 = 0;
                if (i < nc) {
                    int xx, yy;
                    int side = 2 * r + 1;
                    if (i < side)          { xx = cx - r + i;          yy = cy - r; }
                    else if (i < 2 * side) { xx = cx - r + (i - side); yy = cy + r; }
                    else {
                        int j = i - 2 * side;
                        int m = 2 * r - 1;
                        xx = (j < m) ? (cx - r) : (cx + r);
                        yy = cy - r + 1 + (j < m ? j : j - m);
                    }
                    if (xx >= 0 && xx < GG && yy >= 0 && yy < GG) {
                        b2 = yy * GG + xx;
                        c2 = __ldg(&g_cnt[b2]);
                        c2 = c2 < CAP ? c2 : CAP;
                    }
                }
                unsigned mask = __ballot_sync(0xffffffffu, c2 > 0);
                while (mask) {
                    int s = __ffs(mask) - 1;
                    mask &= mask - 1;
                    int bb = __shfl_sync(0xffffffffu, b2, s);
                    int cc = __shfl_sync(0xffffffffu, c2, s);
                    stage_and_scan(bb, cc);
                }
            }
            // All unscanned points lie outside the scanned box; a query at
            // distance dmin from the box boundary is done once bd[8] <= dmin^2.
            float x_lo = -GB + (float)(cx - r) * CS;
            float x_hi = -GB + (float)(cx + r + 1) * CS;
            float y_lo = -GB + (float)(cy - r) * CS;
            float y_hi = -GB + (float)(cy + r + 1) * CS;
            float dmin = fminf(fminf(qx - x_lo, x_hi - qx),
                               fminf(qy - y_lo, y_hi - qy));
            bool done = (!has) || (dmin > 0.0f && bd[KNN - 1] <= dmin * dmin);
            if (__all_sync(0xffffffffu, done)) break;
        }

        if (has) {
#pragma unroll
            for (int p = 0; p < KNN; ++p) g_idx[q * KNN + p] = bi[p];
        }
    }
}

// ---------------------------------------------------------------------------
// GCN layer, warp-per-node:
//  - lanes < CIN gather one channel each; each neighbor row is ONE coalesced
//    transaction; 9 independent loads in flight
//  - mean -> smem agg; lane j computes out[j] via LDS-broadcast + sW FMAs.
template <int CIN, int COUT, bool RELU, bool UPD, bool ZERO, bool BINFILL, bool WOUT>
__global__ void __launch_bounds__(256) k_layer(const float* __restrict__ hin,
                                               const float* __restrict__ W,
                                               float* __restrict__ hout,
                                               float* __restrict__ out2) {
    __shared__ float sW[CIN * COUT];
    __shared__ float sAgg[8][CIN];

    for (int i = threadIdx.x; i < CIN * COUT; i += blockDim.x) sW[i] = W[i];
    __syncthreads();

    const int w    = threadIdx.x >> 5;
    const int lane = threadIdx.x & 31;
    const int n    = blockIdx.x * 8 + w;
    const int gtid = blockIdx.x * blockDim.x + threadIdx.x;

    if (ZERO && gtid < NCELL) g_cnt[gtid] = 0;

    // Gather: 9 coalesced neighbor-row loads, mean over k.
    const int* ip = g_idx + n * KNN;
    int nbreg = (lane < KNN) ? __ldg(&ip[lane]) : 0;

    float vals[KNN];
#pragma unroll
    for (int k = 0; k < KNN; ++k) {
        int nbk = __shfl_sync(0xffffffffu, nbreg, k);
        vals[k] = (lane < CIN) ? __ldg(&hin[nbk * CIN + lane]) : 0.0f;
    }
    float a = 0.0f;
#pragma unroll
    for (int k = 0; k < KNN; ++k) a += vals[k];
    if (lane < CIN) sAgg[w][lane] = a * (1.0f / 9.0f);
    __syncwarp();

    // Matmul: lane j computes output channel j.
    float acc = 0.0f;
    if (lane < COUT) {
#pragma unroll
        for (int c = 0; c < CIN; ++c)
            acc = fmaf(sAgg[w][c], sW[c * COUT + lane], acc);
    }

    float v = acc;
    if (RELU) v = fmaxf(v, 0.0f);
    if (UPD && lane < COUT) v = hout[n * COUT + lane] + v * UPD_RATE;

    if (lane < COUT) {
        hout[n * COUT + lane] = v;
        if (WOUT) out2[n * COUT + lane] = v;
    }
    if (BINFILL) {
        float vy = __shfl_sync(0xffffffffu, v, 1);
        if (lane == 0) bin_insert(v, vy, n);
    }
}

// ---------------------------------------------------------------------------
extern "C" void kernel_launch(void* const* d_in, const int* in_sizes, int n_in,
                              void* d_out, int out_size) {
    const float* seed = (const float*)d_in[0];
    const float* W1   = (const float*)d_in[1];
    const float* W2   = (const float*)d_in[2];
    const float* W3   = (const float*)d_in[3];
    const float* W4   = (const float*)d_in[4];
    float* out = (float*)d_out;

    float *px, *pha, *phb;
    cudaGetSymbolAddress((void**)&px,  g_x);
    cudaGetSymbolAddress((void**)&pha, g_ha);
    cudaGetSymbolAddress((void**)&phb, g_hb);

    constexpr int GL = N_PTS / 8;           // 2048 blocks, warp per node
    constexpr int GK = (NCELL * 32) / 256;  // 2048 blocks, warp per cell

    // step 0
    k_copy_in<<<(N_PTS * C_DIM / 4) / 256, 256>>>(seed);   // + zero counts
    k_binfill<<<N_PTS / 256, 256>>>();
    k_knn<<<GK, 256>>>();
    k_layer<16, 32, true,  false, false, false, false><<<GL, 256>>>(px,  W1, pha, nullptr);
    k_layer<32, 32, true,  false, false, false, false><<<GL, 256>>>(pha, W2, phb, nullptr);
    k_layer<32, 32, true,  false, true,  false, false><<<GL, 256>>>(phb, W3, pha, nullptr); // + zero cnt
    k_layer<32, 16, false, true,  false, true,  false><<<GL, 256>>>(pha, W4, px,  nullptr); // x+=, rebin

    // step 1
    k_knn<<<GK, 256>>>();
    k_layer<16, 32, true,  false, false, false, false><<<GL, 256>>>(px,  W1, pha, nullptr);
    k_layer<32, 32, true,  false, false, false, false><<<GL, 256>>>(pha, W2, phb, nullptr);
    k_layer<32, 32, true,  false, false, false, false><<<GL, 256>>>(phb, W3, pha, nullptr);
    k_layer<32, 16, false, true,  false, false, true ><<<GL, 256>>>(pha, W4, px,  out);     // x+=, writeout
}